// round 1
// baseline (speedup 1.0000x reference)
#include <cuda_runtime.h>
#include <cuda_bf16.h>
#include <cstdint>

// Problem constants (match reference)
#define BATCH 4
#define CHANNELS 64
#define IMG 512
#define HW (IMG * IMG)
#define GRID_RES 64

// 256 MB scratch: pixel_features transposed to NHWC (B, H, W, C)
__device__ float g_nhwc[(size_t)BATCH * HW * CHANNELS];

// ---------------------------------------------------------------------------
// Kernel 1: NCHW -> NHWC transpose.
// Each block handles one batch slice of 64 consecutive hw positions x all 64
// channels, via a 64x64 smem tile. Loads coalesced along hw, stores coalesced
// along c. Grid = BATCH * (HW/64) = 16384 blocks, 256 threads.
// ---------------------------------------------------------------------------
__global__ void __launch_bounds__(256) transpose_nchw_nhwc(const float* __restrict__ in) {
    __shared__ float tile[64][65];

    int block = blockIdx.x;
    int b = block >> 12;                 // HW/64 = 4096 blocks per batch
    int hwbase = (block & 4095) << 6;    // *64

    const float* src = in + (size_t)b * CHANNELS * HW;
    int tid = threadIdx.x;

    // Load: rows = channels, cols = hw (coalesced float4 along hw)
    int c0 = tid >> 4;            // 0..15
    int x4 = (tid & 15) << 2;     // 0..60
#pragma unroll
    for (int cc = c0; cc < 64; cc += 16) {
        float4 v = *(const float4*)(src + (size_t)cc * HW + hwbase + x4);
        tile[cc][x4 + 0] = v.x;
        tile[cc][x4 + 1] = v.y;
        tile[cc][x4 + 2] = v.z;
        tile[cc][x4 + 3] = v.w;
    }
    __syncthreads();

    // Store: rows = hw, cols = channels (coalesced float4 along c)
    int h0 = tid >> 4;            // 0..15
    int c4 = (tid & 15) << 2;     // 0..60
    float* dst = g_nhwc + ((size_t)b * HW + hwbase) * CHANNELS;
#pragma unroll
    for (int h = h0; h < 64; h += 16) {
        float4 v = make_float4(tile[c4 + 0][h], tile[c4 + 1][h],
                               tile[c4 + 2][h], tile[c4 + 3][h]);
        *(float4*)(dst + (size_t)h * CHANNELS + c4) = v;
    }
}

// ---------------------------------------------------------------------------
// Kernel 2: project points + bilinear gather from NHWC features.
// 16 threads per point; each thread covers 4 channels (float4).
// Per corner, the 16 lanes of a point read one contiguous 256B block.
// ---------------------------------------------------------------------------
__global__ void __launch_bounds__(256) project_gather(
    const int* __restrict__ coords,
    const float* __restrict__ Km,
    const float* __restrict__ Pm,
    float* __restrict__ out,
    int N)
{
    __shared__ float sK[9];
    __shared__ float sP[16];
    int tid = threadIdx.x;
    if (tid < 9)  sK[tid] = Km[tid];
    if (tid < 16) sP[tid] = Pm[tid];
    __syncthreads();

    int p = blockIdx.x * 16 + (tid >> 4);   // 16 points per 256-thread block
    int lane = tid & 15;
    if (p >= N) return;

    int4 cd = *(const int4*)(coords + (size_t)p * 4);

    const float scale = 2.0f / (float)(GRID_RES - 1);
    float wx = (float)cd.y * scale - 1.0f;
    float wy = (float)cd.z * scale - 1.0f;
    float wz = (float)cd.w * scale - 1.0f;

    // cam = P @ [wx,wy,wz,1]
    float camx = sP[0]  * wx + sP[1]  * wy + sP[2]  * wz + sP[3];
    float camy = sP[4]  * wx + sP[5]  * wy + sP[6]  * wz + sP[7];
    float camz = sP[8]  * wx + sP[9]  * wy + sP[10] * wz + sP[11];
    float camw = sP[12] * wx + sP[13] * wy + sP[14] * wz + sP[15];
    float invw4 = 1.0f / camw;
    camx *= invw4; camy *= invw4; camz *= invw4;

    // img_h = K @ cam[:3]
    float u = sK[0] * camx + sK[1] * camy + sK[2] * camz;
    float v = sK[3] * camx + sK[4] * camy + sK[5] * camz;
    float w = sK[6] * camx + sK[7] * camy + sK[8] * camz;
    float invw = 1.0f / w;
    float x_real = u * invw;   // -> j (W)
    float y_real = v * invw;   // -> i (H)

    float i_f = floorf(y_real);
    float j_f = floorf(x_real);
    float di = y_real - i_f;
    float dj = x_real - j_f;

    int i0 = min(max((int)i_f, 0), IMG - 1);
    int i1 = min(max((int)i_f + 1, 0), IMG - 1);
    int j0 = min(max((int)j_f, 0), IMG - 1);
    int j1 = min(max((int)j_f + 1, 0), IMG - 1);

    const float* basep = g_nhwc + (size_t)cd.x * HW * CHANNELS;
    int coff = lane << 2;  // 4 channels per lane

    float4 f00 = *(const float4*)(basep + ((size_t)(i0 * IMG + j0)) * CHANNELS + coff);
    float4 f01 = *(const float4*)(basep + ((size_t)(i0 * IMG + j1)) * CHANNELS + coff);
    float4 f10 = *(const float4*)(basep + ((size_t)(i1 * IMG + j0)) * CHANNELS + coff);
    float4 f11 = *(const float4*)(basep + ((size_t)(i1 * IMG + j1)) * CHANNELS + coff);

    float w00 = (1.0f - di) * (1.0f - dj);
    float w10 = di * (1.0f - dj);
    float w01 = (1.0f - di) * dj;
    float w11 = di * dj;

    float4 r;
    r.x = w00 * f00.x + w10 * f10.x + w01 * f01.x + w11 * f11.x;
    r.y = w00 * f00.y + w10 * f10.y + w01 * f01.y + w11 * f11.y;
    r.z = w00 * f00.z + w10 * f10.z + w01 * f01.z + w11 * f11.z;
    r.w = w00 * f00.w + w10 * f10.w + w01 * f01.w + w11 * f11.w;

    *(float4*)(out + (size_t)p * CHANNELS + coff) = r;

    if (lane == 0) {
        out[(size_t)N * CHANNELS + p] = camz;  // depth = cam[2] after /cam[3]
    }
}

extern "C" void kernel_launch(void* const* d_in, const int* in_sizes, int n_in,
                              void* d_out, int out_size) {
    const int*   coords = (const int*)d_in[0];
    const float* feats  = (const float*)d_in[1];
    const float* Km     = (const float*)d_in[2];
    const float* Pm     = (const float*)d_in[3];
    float* out = (float*)d_out;

    int N = in_sizes[0] / 4;

    // 1) transpose features to NHWC scratch
    transpose_nchw_nhwc<<<BATCH * (HW / 64), 256>>>(feats);

    // 2) project + gather
    int blocks = (N + 15) / 16;
    project_gather<<<blocks, 256>>>(coords, Km, Pm, out, N);
}

// round 2
// speedup vs baseline: 1.0465x; 1.0465x over previous
#include <cuda_runtime.h>
#include <cuda_bf16.h>
#include <cstdint>

// Problem constants (match reference)
#define BATCH 4
#define CHANNELS 64
#define IMG 512
#define HW (IMG * IMG)
#define GRID_RES 64

// 256 MB scratch: pixel_features transposed to NHWC (B, H, W, C)
__device__ float g_nhwc[(size_t)BATCH * HW * CHANNELS];

// ---------------------------------------------------------------------------
// Kernel 1: NCHW -> NHWC transpose (64x64 smem tile, coalesced both sides).
// ---------------------------------------------------------------------------
__global__ void __launch_bounds__(256) transpose_nchw_nhwc(const float* __restrict__ in) {
    __shared__ float tile[64][65];

    int block = blockIdx.x;
    int b = block >> 12;                 // HW/64 = 4096 blocks per batch
    int hwbase = (block & 4095) << 6;    // *64

    const float* src = in + (size_t)b * CHANNELS * HW;
    int tid = threadIdx.x;

    int c0 = tid >> 4;            // 0..15
    int x4 = (tid & 15) << 2;     // 0..60
#pragma unroll
    for (int cc = c0; cc < 64; cc += 16) {
        float4 v = *(const float4*)(src + (size_t)cc * HW + hwbase + x4);
        tile[cc][x4 + 0] = v.x;
        tile[cc][x4 + 1] = v.y;
        tile[cc][x4 + 2] = v.z;
        tile[cc][x4 + 3] = v.w;
    }
    __syncthreads();

    int h0 = tid >> 4;            // 0..15
    int c4 = (tid & 15) << 2;     // 0..60
    float* dst = g_nhwc + ((size_t)b * HW + hwbase) * CHANNELS;
#pragma unroll
    for (int h = h0; h < 64; h += 16) {
        float4 v = make_float4(tile[c4 + 0][h], tile[c4 + 1][h],
                               tile[c4 + 2][h], tile[c4 + 3][h]);
        *(float4*)(dst + (size_t)h * CHANNELS + c4) = v;
    }
}

// ---------------------------------------------------------------------------
// Kernel 2: two-phase project + gather.
// Phase 1: 1 thread = 1 point (256 points/block). Projection math computed
//          ONCE per point; depth written coalesced; {i_f, j_f, di, dj, base}
//          parked in smem.
// Phase 2: 16 lanes = 1 point, 16 iterations. Pure gather: 4 independent
//          float4 corner loads + weighted sum + coalesced float4 store.
// ---------------------------------------------------------------------------
__global__ void __launch_bounds__(256) project_gather(
    const int* __restrict__ coords,
    const float* __restrict__ Km,
    const float* __restrict__ Pm,
    float* __restrict__ out,
    int N)
{
    __shared__ float4 s_pt[256];    // {i_f, j_f, di, dj}
    __shared__ int    s_base[256];  // batch * HW * CHANNELS (element offset)
    __shared__ float  sK[9];
    __shared__ float  sP[16];

    int tid = threadIdx.x;
    if (tid < 9)       sK[tid] = Km[tid];
    else if (tid < 25) sP[tid - 9] = Pm[tid - 9];
    __syncthreads();

    int base = blockIdx.x << 8;     // 256 points per block
    int p = base + tid;

    // ---- Phase 1: projection (one thread per point) ----
    if (p < N) {
        int4 cd = *(const int4*)(coords + (size_t)p * 4);

        const float scale = 2.0f / (float)(GRID_RES - 1);
        float wx = (float)cd.y * scale - 1.0f;
        float wy = (float)cd.z * scale - 1.0f;
        float wz = (float)cd.w * scale - 1.0f;

        float camx = sP[0]  * wx + sP[1]  * wy + sP[2]  * wz + sP[3];
        float camy = sP[4]  * wx + sP[5]  * wy + sP[6]  * wz + sP[7];
        float camz = sP[8]  * wx + sP[9]  * wy + sP[10] * wz + sP[11];
        float camw = sP[12] * wx + sP[13] * wy + sP[14] * wz + sP[15];
        float invw4 = 1.0f / camw;
        camx *= invw4; camy *= invw4; camz *= invw4;

        float u = sK[0] * camx + sK[1] * camy + sK[2] * camz;
        float v = sK[3] * camx + sK[4] * camy + sK[5] * camz;
        float w = sK[6] * camx + sK[7] * camy + sK[8] * camz;
        float invw = 1.0f / w;
        float x_real = u * invw;   // -> j (W)
        float y_real = v * invw;   // -> i (H)

        // depth, coalesced across the block
        out[(size_t)N * CHANNELS + p] = camz;

        float i_f = floorf(y_real);
        float j_f = floorf(x_real);
        s_pt[tid] = make_float4(i_f, j_f, y_real - i_f, x_real - j_f);
        s_base[tid] = cd.x * (HW * CHANNELS);
    }
    __syncthreads();

    // ---- Phase 2: gather (16 lanes per point) ----
    int lane = tid & 15;
    int grp  = tid >> 4;
    int npts = min(256, N - base);
    int coff = lane << 2;

#pragma unroll 4
    for (int it = 0; it < 16; it++) {
        int pp = grp + (it << 4);
        if (pp >= npts) break;

        float4 pt = s_pt[pp];
        int fb = s_base[pp];

        int ii = (int)pt.x;
        int jj = (int)pt.y;
        int i0 = min(max(ii, 0), IMG - 1);
        int i1 = min(max(ii + 1, 0), IMG - 1);
        int j0 = min(max(jj, 0), IMG - 1);
        int j1 = min(max(jj + 1, 0), IMG - 1);
        float di = pt.z;
        float dj = pt.w;

        const float* bp = g_nhwc + fb + coff;
        int r0 = i0 << 15;   // i0 * IMG * CHANNELS
        int r1 = i1 << 15;
        int c0 = j0 << 6;    // j0 * CHANNELS
        int c1 = j1 << 6;

        float4 f00 = *(const float4*)(bp + r0 + c0);
        float4 f01 = *(const float4*)(bp + r0 + c1);
        float4 f10 = *(const float4*)(bp + r1 + c0);
        float4 f11 = *(const float4*)(bp + r1 + c1);

        float w00 = (1.0f - di) * (1.0f - dj);
        float w10 = di * (1.0f - dj);
        float w01 = (1.0f - di) * dj;
        float w11 = di * dj;

        float4 r;
        r.x = w00 * f00.x + w10 * f10.x + w01 * f01.x + w11 * f11.x;
        r.y = w00 * f00.y + w10 * f10.y + w01 * f01.y + w11 * f11.y;
        r.z = w00 * f00.z + w10 * f10.z + w01 * f01.z + w11 * f11.z;
        r.w = w00 * f00.w + w10 * f10.w + w01 * f01.w + w11 * f11.w;

        *(float4*)(out + ((size_t)(base + pp) << 6) + coff) = r;
    }
}

extern "C" void kernel_launch(void* const* d_in, const int* in_sizes, int n_in,
                              void* d_out, int out_size) {
    const int*   coords = (const int*)d_in[0];
    const float* feats  = (const float*)d_in[1];
    const float* Km     = (const float*)d_in[2];
    const float* Pm     = (const float*)d_in[3];
    float* out = (float*)d_out;

    int N = in_sizes[0] / 4;

    transpose_nchw_nhwc<<<BATCH * (HW / 64), 256>>>(feats);

    int blocks = (N + 255) / 256;
    project_gather<<<blocks, 256>>>(coords, Km, Pm, out, N);
}

// round 3
// speedup vs baseline: 1.6180x; 1.5462x over previous
#include <cuda_runtime.h>
#include <cuda_fp16.h>
#include <cstdint>

// Problem constants (match reference)
#define BATCH 4
#define CHANNELS 64
#define IMG 512
#define HW (IMG * IMG)
#define GRID_RES 64

// 128 MB scratch: pixel_features transposed to NHWC (B, H, W, C) in fp16.
// ~L2-sized (126 MB) so the gather's random reads mostly hit L2.
__device__ __half g_nhwc[(size_t)BATCH * HW * CHANNELS];

// ---------------------------------------------------------------------------
// Kernel 1: NCHW fp32 -> NHWC fp16 transpose (64x64 smem tile).
// Loads coalesced along hw, stores coalesced along c.
// ---------------------------------------------------------------------------
__global__ void __launch_bounds__(256) transpose_nchw_nhwc(const float* __restrict__ in) {
    __shared__ float tile[64][65];

    int block = blockIdx.x;
    int b = block >> 12;                 // HW/64 = 4096 blocks per batch
    int hwbase = (block & 4095) << 6;    // *64

    const float* src = in + (size_t)b * CHANNELS * HW;
    int tid = threadIdx.x;

    int c0 = tid >> 4;            // 0..15
    int x4 = (tid & 15) << 2;     // 0..60
#pragma unroll
    for (int cc = c0; cc < 64; cc += 16) {
        float4 v = *(const float4*)(src + (size_t)cc * HW + hwbase + x4);
        tile[cc][x4 + 0] = v.x;
        tile[cc][x4 + 1] = v.y;
        tile[cc][x4 + 2] = v.z;
        tile[cc][x4 + 3] = v.w;
    }
    __syncthreads();

    // Store: rows = hw, cols = channels, fp16. Each thread writes 4 halves (8B).
    int h0 = tid >> 4;            // 0..15
    int c4 = (tid & 15) << 2;     // 0..60
    __half* dst = g_nhwc + ((size_t)b * HW + hwbase) * CHANNELS;
#pragma unroll
    for (int h = h0; h < 64; h += 16) {
        __half2 lo = __floats2half2_rn(tile[c4 + 0][h], tile[c4 + 1][h]);
        __half2 hi = __floats2half2_rn(tile[c4 + 2][h], tile[c4 + 3][h]);
        uint2 v;
        v.x = *(const unsigned int*)&lo;
        v.y = *(const unsigned int*)&hi;
        *(uint2*)(dst + (size_t)h * CHANNELS + c4) = v;
    }
}

// ---------------------------------------------------------------------------
// Kernel 2: two-phase project + gather.
// Phase 1: 1 thread = 1 point. Projection once; depth written coalesced
//          (streaming); {i_f, j_f, di, dj} + feature base in smem.
// Phase 2: 8 lanes = 1 point. Each lane loads 8 fp16 channels (uint4,
//          LDG.128) per corner, converts, blends, stores 2x float4
//          (streaming, keep L2 for features).
// ---------------------------------------------------------------------------
__global__ void __launch_bounds__(256) project_gather(
    const int* __restrict__ coords,
    const float* __restrict__ Km,
    const float* __restrict__ Pm,
    float* __restrict__ out,
    int N)
{
    __shared__ float4 s_pt[256];    // {i_f, j_f, di, dj}
    __shared__ int    s_base[256];  // batch * HW * CHANNELS (element offset)
    __shared__ float  sK[9];
    __shared__ float  sP[16];

    int tid = threadIdx.x;
    if (tid < 9)       sK[tid] = Km[tid];
    else if (tid < 25) sP[tid - 9] = Pm[tid - 9];
    __syncthreads();

    int base = blockIdx.x << 8;     // 256 points per block
    int p = base + tid;

    // ---- Phase 1: projection ----
    if (p < N) {
        int4 cd = __ldcs((const int4*)(coords + (size_t)p * 4));

        const float scale = 2.0f / (float)(GRID_RES - 1);
        float wx = (float)cd.y * scale - 1.0f;
        float wy = (float)cd.z * scale - 1.0f;
        float wz = (float)cd.w * scale - 1.0f;

        float camx = sP[0]  * wx + sP[1]  * wy + sP[2]  * wz + sP[3];
        float camy = sP[4]  * wx + sP[5]  * wy + sP[6]  * wz + sP[7];
        float camz = sP[8]  * wx + sP[9]  * wy + sP[10] * wz + sP[11];
        float camw = sP[12] * wx + sP[13] * wy + sP[14] * wz + sP[15];
        float invw4 = 1.0f / camw;
        camx *= invw4; camy *= invw4; camz *= invw4;

        float u = sK[0] * camx + sK[1] * camy + sK[2] * camz;
        float v = sK[3] * camx + sK[4] * camy + sK[5] * camz;
        float w = sK[6] * camx + sK[7] * camy + sK[8] * camz;
        float invw = 1.0f / w;
        float x_real = u * invw;   // -> j (W)
        float y_real = v * invw;   // -> i (H)

        __stcs(out + (size_t)N * CHANNELS + p, camz);  // depth, coalesced

        float i_f = floorf(y_real);
        float j_f = floorf(x_real);
        s_pt[tid] = make_float4(i_f, j_f, y_real - i_f, x_real - j_f);
        s_base[tid] = cd.x * (HW * CHANNELS);
    }
    __syncthreads();

    // ---- Phase 2: gather (8 lanes per point) ----
    int lane = tid & 7;
    int grp  = tid >> 3;            // 32 point-groups
    int npts = min(256, N - base);
    int coff = lane << 3;           // 8 channels per lane

#pragma unroll
    for (int it = 0; it < 8; it++) {
        int pp = grp + (it << 5);
        if (pp >= npts) break;

        float4 pt = s_pt[pp];
        int fb = s_base[pp];

        int ii = (int)pt.x;
        int jj = (int)pt.y;
        int i0 = min(max(ii, 0), IMG - 1);
        int i1 = min(max(ii + 1, 0), IMG - 1);
        int j0 = min(max(jj, 0), IMG - 1);
        int j1 = min(max(jj + 1, 0), IMG - 1);
        float di = pt.z;
        float dj = pt.w;

        const __half* bp = g_nhwc + fb + coff;
        int r0 = i0 << 15;   // i * IMG * CHANNELS
        int r1 = i1 << 15;
        int c0 = j0 << 6;    // j * CHANNELS
        int c1 = j1 << 6;

        uint4 a00 = *(const uint4*)(bp + r0 + c0);
        uint4 a01 = *(const uint4*)(bp + r0 + c1);
        uint4 a10 = *(const uint4*)(bp + r1 + c0);
        uint4 a11 = *(const uint4*)(bp + r1 + c1);

        float w00 = (1.0f - di) * (1.0f - dj);
        float w10 = di * (1.0f - dj);
        float w01 = (1.0f - di) * dj;
        float w11 = di * dj;

        const unsigned int* u00 = (const unsigned int*)&a00;
        const unsigned int* u01 = (const unsigned int*)&a01;
        const unsigned int* u10 = (const unsigned int*)&a10;
        const unsigned int* u11 = (const unsigned int*)&a11;

        float res[8];
#pragma unroll
        for (int k = 0; k < 4; k++) {
            float2 f00 = __half22float2(*(const __half2*)&u00[k]);
            float2 f01 = __half22float2(*(const __half2*)&u01[k]);
            float2 f10 = __half22float2(*(const __half2*)&u10[k]);
            float2 f11 = __half22float2(*(const __half2*)&u11[k]);
            res[2*k]   = w00 * f00.x + w10 * f10.x + w01 * f01.x + w11 * f11.x;
            res[2*k+1] = w00 * f00.y + w10 * f10.y + w01 * f01.y + w11 * f11.y;
        }

        float* op = out + ((size_t)(base + pp) << 6) + coff;
        __stcs((float4*)op,     make_float4(res[0], res[1], res[2], res[3]));
        __stcs((float4*)op + 1, make_float4(res[4], res[5], res[6], res[7]));
    }
}

extern "C" void kernel_launch(void* const* d_in, const int* in_sizes, int n_in,
                              void* d_out, int out_size) {
    const int*   coords = (const int*)d_in[0];
    const float* feats  = (const float*)d_in[1];
    const float* Km     = (const float*)d_in[2];
    const float* Pm     = (const float*)d_in[3];
    float* out = (float*)d_out;

    int N = in_sizes[0] / 4;

    transpose_nchw_nhwc<<<BATCH * (HW / 64), 256>>>(feats);

    int blocks = (N + 255) / 256;
    project_gather<<<blocks, 256>>>(coords, Km, Pm, out, N);
}